// round 9
// baseline (speedup 1.0000x reference)
#include <cuda_runtime.h>

// Problem constants
#define DD 32
#define HH 128
#define WW 128
#define OD 26
#define OH 122
#define OW 122
#define TZ 2
#define TY 2
#define TXT 32            // threads along x
#define PX 2              // output voxels per thread along x (f32x2 pairing)
#define TXO (TXT * PX)    // 64 output columns per block
#define NTHREADS 128

#define GW (TXO + 6)      // 70 (even -> rows stay 8B aligned)
#define XW (TXO + 2)      // 66

typedef unsigned long long u64;

// ---- packed f32x2 helpers -------------------------------------------------
__device__ __forceinline__ u64 pack2(float lo, float hi) {
    u64 r; asm("mov.b64 %0, {%1, %2};" : "=l"(r) : "f"(lo), "f"(hi)); return r;
}
__device__ __forceinline__ void unpack2(u64 v, float& a, float& b) {
    asm("mov.b64 {%0, %1}, %2;" : "=f"(a), "=f"(b) : "l"(v));
}
__device__ __forceinline__ u64 fma2(u64 a, u64 b, u64 c) {
    u64 d; asm("fma.rn.f32x2 %0, %1, %2, %3;" : "=l"(d) : "l"(a), "l"(b), "l"(c)); return d;
}
__device__ __forceinline__ u64 add2(u64 a, u64 b) {
    u64 d; asm("add.rn.f32x2 %0, %1, %2;" : "=l"(d) : "l"(a), "l"(b)); return d;
}
__device__ __forceinline__ u64 abs2(u64 a) {
    u64 d; asm("and.b64 %0, %1, 0x7FFFFFFF7FFFFFFF;" : "=l"(d) : "l"(a)); return d;
}
__device__ __forceinline__ u64 relu2(u64 a) {
    float x, y; unpack2(a, x, y);
    return pack2(fmaxf(x, 0.f), fmaxf(y, 0.f));
}

// ---------------------------------------------------------------------------
// Staged parameter block: built on device by the pre-kernel, then copied D2D
// into __constant__ (graph-capturable memcpy node). Constant operands reach
// the FFMA2s through LDCU/uniform registers -> no GPR cost, no RF-bank cost.
// ---------------------------------------------------------------------------
struct WPack {
    u64 w0p[27];
    u64 w1p[27];
    u64 b0p, b1p;
    float dk[27];
};
__device__   WPack g_stage;
__constant__ WPack c_pack;

// ---------------------------------------------------------------------------
// Pre-kernel: packs range weights/biases and computes the domain kernel
// dk = relu(conv(relu(conv(dn, dw0)+db0), dw1)+db1),
// dn = domain_neighbor[0,0,1:8,1:8,1:8]  (M=9, cx=1)
// ---------------------------------------------------------------------------
__global__ void dk_kernel(const float* __restrict__ dn,
                          const float* __restrict__ dw0, const float* __restrict__ db0,
                          const float* __restrict__ dw1, const float* __restrict__ db1,
                          const float* __restrict__ rw0, const float* __restrict__ rb0,
                          const float* __restrict__ rw1, const float* __restrict__ rb1)
{
    __shared__ float s0[125];
    int t = threadIdx.x;
    if (t < 27) {
        float a = rw0[t]; g_stage.w0p[t] = pack2(a, a);
        float b = rw1[t]; g_stage.w1p[t] = pack2(b, b);
    }
    if (t == 0) {
        float b0 = rb0[0], b1 = rb1[0];
        g_stage.b0p = pack2(b0, b0);
        g_stage.b1p = pack2(b1, b1);
    }
    if (t < 125) {
        int iz = t / 25, iy = (t / 5) % 5, ix = t % 5;
        float acc = db0[0];
#pragma unroll
        for (int dz = 0; dz < 3; dz++)
#pragma unroll
            for (int dy = 0; dy < 3; dy++)
#pragma unroll
                for (int dx = 0; dx < 3; dx++) {
                    float v = dn[((1 + iz + dz) * 9 + (1 + iy + dy)) * 9 + (1 + ix + dx)];
                    acc += v * dw0[(dz * 3 + dy) * 3 + dx];
                }
        s0[t] = fmaxf(acc, 0.f);
    }
    __syncthreads();
    if (t < 27) {
        int jz = t / 9, jy = (t / 3) % 3, jx = t % 3;
        float acc = db1[0];
#pragma unroll
        for (int dz = 0; dz < 3; dz++)
#pragma unroll
            for (int dy = 0; dy < 3; dy++)
#pragma unroll
                for (int dx = 0; dx < 3; dx++)
                    acc += s0[((jz + dz) * 5 + (jy + dy)) * 5 + (jx + dx)]
                         * dw1[(dz * 3 + dy) * 3 + dx];
        g_stage.dk[t] = fmaxf(acc, 0.f);
    }
}

// ---------------------------------------------------------------------------
// Main kernel: each thread computes TWO x-adjacent output voxels with packed
// f32x2 math. Weights come from __constant__ (uniform-register path). gs2 is
// a 1-element-shifted copy of gs so every (c, c+1) pair load is an aligned
// LDS.64 regardless of parity.
// ---------------------------------------------------------------------------
__global__ __launch_bounds__(NTHREADS, 3)
void jbf_kernel(const float* __restrict__ x, const float* __restrict__ guide,
                float* __restrict__ out)
{
    __shared__ __align__(16) float gs [TZ + 6][TY + 6][GW];
    __shared__ __align__(16) float gs2[TZ + 6][TY + 6][GW];   // gs2[c] = gs[c+1]
    __shared__ float xs[TZ + 2][TY + 2][XW];

    const int tid = threadIdx.x;
    const int tx = tid & 31;
    const int ty = (tid >> 5) & 1;
    const int tz = tid >> 6;
    const int z0 = blockIdx.z * TZ;
    const int y0 = blockIdx.y * TY;
    const int x0 = blockIdx.x * TXO;

    // ---- cooperative tile loads ----
    const int GT = (TZ + 6) * (TY + 6) * GW;   // 4480
    for (int i = tid; i < GT; i += NTHREADS) {
        int c = i % GW;
        int r = i / GW;
        int b = r % (TY + 6);
        int a = r / (TY + 6);
        int gx = x0 + c;
        float v = (gx < WW) ? guide[((z0 + a) * HH + (y0 + b)) * WW + gx] : 0.f;
        gs[a][b][c] = v;
        if (c > 0) gs2[a][b][c - 1] = v;
    }
    const int XT = (TZ + 2) * (TY + 2) * XW;   // 1056
    for (int i = tid; i < XT; i += NTHREADS) {
        int c = i % XW;
        int r = i / XW;
        int b = r % (TY + 2);
        int a = r / (TY + 2);
        int gx = x0 + 2 + c;
        float v = (gx < WW) ? x[((z0 + 2 + a) * HH + (y0 + 2 + b)) * WW + gx] : 0.f;
        xs[a][b][c] = v;
    }
    __syncthreads();

    const int j0  = 2 * tx;          // local x of voxel 0 (even)
    const int ox0 = x0 + j0;
    if (ox0 >= OW) return;           // ox0 even -> ox0+1 <= 121 always valid
    const int oz = z0 + tz;
    const int oy = y0 + ty;

    const u64 b0p = c_pack.b0p;
    const u64 b1p = c_pack.b1p;

    const float C0 = gs[tz + 3][ty + 3][j0 + 3];
    const float C1 = gs[tz + 3][ty + 3][j0 + 4];
    const u64 negC = pack2(-C0, -C1);

    u64 rk[27];
#pragma unroll
    for (int j = 0; j < 27; j++) rk[j] = b1p;

    // ---- stage A (7^3 -> 5^3) chunked by output z-plane, fused with stage B ----
#pragma unroll
    for (int iz = 0; iz < 5; iz++) {
        u64 p[25];
#pragma unroll
        for (int k = 0; k < 25; k++) p[k] = b0p;

#pragma unroll
        for (int dz = 0; dz < 3; dz++) {
#pragma unroll
            for (int b = 0; b < 7; b++) {
                const float* rowA = &gs [tz + iz + dz][ty + b][j0];
                const float* rowB = &gs2[tz + iz + dz][ty + b][j0];
#pragma unroll
                for (int c = 0; c < 7; c++) {
                    u64 g2 = ((c & 1) == 0)
                           ? *reinterpret_cast<const u64*>(rowA + c)
                           : *reinterpret_cast<const u64*>(rowB + c - 1);
                    u64 t = abs2(add2(g2, negC));
#pragma unroll
                    for (int dy = 0; dy < 3; dy++) {
                        int iy = b - dy;
                        if (iy < 0 || iy >= 5) continue;
#pragma unroll
                        for (int dx = 0; dx < 3; dx++) {
                            int ix = c - dx;
                            if (ix < 0 || ix >= 5) continue;
                            p[iy * 5 + ix] = fma2(t, c_pack.w0p[(dz * 3 + dy) * 3 + dx],
                                                  p[iy * 5 + ix]);
                        }
                    }
                }
            }
        }
#pragma unroll
        for (int k = 0; k < 25; k++) p[k] = relu2(p[k]);

        // stage B partial consume
#pragma unroll
        for (int jz = 0; jz < 3; jz++) {
            int dz2 = iz - jz;
            if (dz2 < 0 || dz2 >= 3) continue;
#pragma unroll
            for (int jy = 0; jy < 3; jy++)
#pragma unroll
                for (int dy = 0; dy < 3; dy++)
#pragma unroll
                    for (int jx = 0; jx < 3; jx++)
#pragma unroll
                        for (int dx = 0; dx < 3; dx++)
                            rk[(jz * 3 + jy) * 3 + jx] =
                                fma2(c_pack.w1p[(dz2 * 3 + dy) * 3 + dx],
                                     p[(jy + dy) * 5 + (jx + dx)],
                                     rk[(jz * 3 + jy) * 3 + jx]);
        }
    }

    // ---- epilogue: weights = dk * relu(rk) + 1e-10; weighted average of x ----
    float num0 = 0.f, den0 = 0.f, num1 = 0.f, den1 = 0.f;
#pragma unroll
    for (int j = 0; j < 27; j++) {
        int jz = j / 9, jy = (j / 3) % 3, jx = j % 3;
        float r0, r1;
        unpack2(rk[j], r0, r1);
        float dk = c_pack.dk[j];
        float wv0 = dk * fmaxf(r0, 0.f) + 1e-10f;
        float wv1 = dk * fmaxf(r1, 0.f) + 1e-10f;
        num0 += xs[tz + jz][ty + jy][j0 + jx] * wv0;
        den0 += wv0;
        num1 += xs[tz + jz][ty + jy][j0 + 1 + jx] * wv1;
        den1 += wv1;
    }
    float* o = &out[(oz * OH + oy) * OW + ox0];
    o[0] = num0 / den0;
    o[1] = num1 / den1;
}

// ---------------------------------------------------------------------------
// inputs (metadata order): x, domain_neighbor, guide_im, rw0, rb0, rw1, rb1,
//                          dw0, db0, dw1, db1
// ---------------------------------------------------------------------------
extern "C" void kernel_launch(void* const* d_in, const int* in_sizes, int n_in,
                              void* d_out, int out_size)
{
    const float* x     = (const float*)d_in[0];
    const float* dn    = (const float*)d_in[1];
    const float* guide = (const float*)d_in[2];
    const float* rw0   = (const float*)d_in[3];
    const float* rb0   = (const float*)d_in[4];
    const float* rw1   = (const float*)d_in[5];
    const float* rb1   = (const float*)d_in[6];
    const float* dw0   = (const float*)d_in[7];
    const float* db0   = (const float*)d_in[8];
    const float* dw1   = (const float*)d_in[9];
    const float* db1   = (const float*)d_in[10];
    float* out = (float*)d_out;

    // 1) build packed weights + domain kernel on device
    dk_kernel<<<1, 128>>>(dn, dw0, db0, dw1, db1, rw0, rb0, rw1, rb1);

    // 2) stage -> __constant__ (device-to-device async copy: graph-capturable)
    void* src = nullptr;
    cudaGetSymbolAddress(&src, g_stage);
    cudaMemcpyToSymbolAsync(c_pack, src, sizeof(WPack), 0,
                            cudaMemcpyDeviceToDevice, 0);

    // 3) main kernel
    dim3 grid((OW + TXO - 1) / TXO, OH / TY, OD / TZ);   // 2 x 61 x 13
    jbf_kernel<<<grid, NTHREADS>>>(x, guide, out);
}

// round 10
// speedup vs baseline: 1.8372x; 1.8372x over previous
#include <cuda_runtime.h>

// Problem constants
#define DD 32
#define HH 128
#define WW 128
#define OD 26
#define OH 122
#define OW 122
#define TZ 2
#define TY 2
#define TXT 32            // threads along x
#define PX 2              // output voxels per thread along x (f32x2 pairing)
#define TXO (TXT * PX)    // 64 output columns per block
#define NTHREADS 128

#define GW (TXO + 6)      // 70 (even -> rows stay 8B aligned)
#define XW (TXO + 2)      // 66

typedef unsigned long long u64;

// Domain kernel (3x3x3), computed once per launch by dk_kernel.
__device__ float g_dk[27];

// ---- packed f32x2 helpers -------------------------------------------------
__device__ __forceinline__ u64 pack2(float lo, float hi) {
    u64 r; asm("mov.b64 %0, {%1, %2};" : "=l"(r) : "f"(lo), "f"(hi)); return r;
}
// volatile variant: pinned at its call site (no hoist / no CSE across chunks)
__device__ __forceinline__ u64 pack2v(float lo, float hi) {
    u64 r; asm volatile("mov.b64 %0, {%1, %2};" : "=l"(r) : "f"(lo), "f"(hi)); return r;
}
__device__ __forceinline__ void unpack2(u64 v, float& a, float& b) {
    asm("mov.b64 {%0, %1}, %2;" : "=f"(a), "=f"(b) : "l"(v));
}
__device__ __forceinline__ u64 fma2(u64 a, u64 b, u64 c) {
    u64 d; asm("fma.rn.f32x2 %0, %1, %2, %3;" : "=l"(d) : "l"(a), "l"(b), "l"(c)); return d;
}
__device__ __forceinline__ u64 add2(u64 a, u64 b) {
    u64 d; asm("add.rn.f32x2 %0, %1, %2;" : "=l"(d) : "l"(a), "l"(b)); return d;
}
__device__ __forceinline__ u64 abs2(u64 a) {
    u64 d; asm("and.b64 %0, %1, 0x7FFFFFFF7FFFFFFF;" : "=l"(d) : "l"(a)); return d;
}
__device__ __forceinline__ u64 relu2(u64 a) {
    float x, y; unpack2(a, x, y);
    return pack2(fmaxf(x, 0.f), fmaxf(y, 0.f));
}

// ---------------------------------------------------------------------------
// Tiny pre-kernel: dk = relu(conv(relu(conv(dn, dw0)+db0), dw1)+db1)
// dn = domain_neighbor[0,0,1:8,1:8,1:8]  (M=9, cx=1)
// ---------------------------------------------------------------------------
__global__ void dk_kernel(const float* __restrict__ dn,
                          const float* __restrict__ dw0, const float* __restrict__ db0,
                          const float* __restrict__ dw1, const float* __restrict__ db1)
{
    __shared__ float s0[125];
    int t = threadIdx.x;
    if (t < 125) {
        int iz = t / 25, iy = (t / 5) % 5, ix = t % 5;
        float acc = db0[0];
#pragma unroll
        for (int dz = 0; dz < 3; dz++)
#pragma unroll
            for (int dy = 0; dy < 3; dy++)
#pragma unroll
                for (int dx = 0; dx < 3; dx++) {
                    float v = dn[((1 + iz + dz) * 9 + (1 + iy + dy)) * 9 + (1 + ix + dx)];
                    acc += v * dw0[(dz * 3 + dy) * 3 + dx];
                }
        s0[t] = fmaxf(acc, 0.f);
    }
    __syncthreads();
    if (t < 27) {
        int jz = t / 9, jy = (t / 3) % 3, jx = t % 3;
        float acc = db1[0];
#pragma unroll
        for (int dz = 0; dz < 3; dz++)
#pragma unroll
            for (int dy = 0; dy < 3; dy++)
#pragma unroll
                for (int dx = 0; dx < 3; dx++)
                    acc += s0[((jz + dz) * 5 + (jy + dy)) * 5 + (jx + dx)]
                         * dw1[(dz * 3 + dy) * 3 + dx];
        g_dk[t] = fmaxf(acc, 0.f);
    }
}

// ---------------------------------------------------------------------------
// Main kernel: each thread computes TWO x-adjacent output voxels with packed
// f32x2 math. Weights are held as SCALAR floats (27+27 regs); the 9 packed
// pairs a chunk needs are materialized inside the chunk body with volatile
// movs so their live range stays chunk-local. gs2 is a 1-element-shifted
// copy of gs so every (c, c+1) pair load is an aligned LDS.64.
// ---------------------------------------------------------------------------
__global__ __launch_bounds__(NTHREADS, 3)
void jbf_kernel(const float* __restrict__ x, const float* __restrict__ guide,
                const float* __restrict__ rw0, const float* __restrict__ rb0,
                const float* __restrict__ rw1, const float* __restrict__ rb1,
                float* __restrict__ out)
{
    __shared__ __align__(16) float gs [TZ + 6][TY + 6][GW];
    __shared__ __align__(16) float gs2[TZ + 6][TY + 6][GW];   // gs2[c] = gs[c+1]
    __shared__ float xs[TZ + 2][TY + 2][XW];

    const int tid = threadIdx.x;
    const int tx = tid & 31;
    const int ty = (tid >> 5) & 1;
    const int tz = tid >> 6;
    const int z0 = blockIdx.z * TZ;
    const int y0 = blockIdx.y * TY;
    const int x0 = blockIdx.x * TXO;

    // ---- cooperative tile loads ----
    const int GT = (TZ + 6) * (TY + 6) * GW;   // 4480
    for (int i = tid; i < GT; i += NTHREADS) {
        int c = i % GW;
        int r = i / GW;
        int b = r % (TY + 6);
        int a = r / (TY + 6);
        int gx = x0 + c;
        float v = (gx < WW) ? guide[((z0 + a) * HH + (y0 + b)) * WW + gx] : 0.f;
        gs[a][b][c] = v;
        if (c > 0) gs2[a][b][c - 1] = v;
    }
    const int XT = (TZ + 2) * (TY + 2) * XW;   // 1056
    for (int i = tid; i < XT; i += NTHREADS) {
        int c = i % XW;
        int r = i / XW;
        int b = r % (TY + 2);
        int a = r / (TY + 2);
        int gx = x0 + 2 + c;
        float v = (gx < WW) ? x[((z0 + 2 + a) * HH + (y0 + 2 + b)) * WW + gx] : 0.f;
        xs[a][b][c] = v;
    }
    __syncthreads();

    const int j0  = 2 * tx;          // local x of voxel 0 (even)
    const int ox0 = x0 + j0;
    if (ox0 >= OW) return;           // ox0 even -> ox0+1 <= 121 always valid
    const int oz = z0 + tz;
    const int oy = y0 + ty;

    // scalar weights in registers (uniform loads, L1-broadcast)
    float w0s[27], w1s[27];
#pragma unroll
    for (int i = 0; i < 27; i++) w0s[i] = rw0[i];
#pragma unroll
    for (int i = 0; i < 27; i++) w1s[i] = rw1[i];
    const float b0 = rb0[0];
    const float b1 = rb1[0];

    const float C0 = gs[tz + 3][ty + 3][j0 + 3];
    const float C1 = gs[tz + 3][ty + 3][j0 + 4];
    const u64 negC = pack2(-C0, -C1);

    u64 rk[27];
    {
        const u64 b1p = pack2(b1, b1);
#pragma unroll
        for (int j = 0; j < 27; j++) rk[j] = b1p;
    }

    // ---- stage A (7^3 -> 5^3) chunked by output z-plane, fused with stage B ----
#pragma unroll
    for (int iz = 0; iz < 5; iz++) {
        u64 p[25];
        {
            const u64 b0p = pack2v(b0, b0);
#pragma unroll
            for (int k = 0; k < 25; k++) p[k] = b0p;
        }

#pragma unroll
        for (int dz = 0; dz < 3; dz++) {
            // chunk-local packed weights (volatile: not hoisted across chunks)
            u64 wA[9];
#pragma unroll
            for (int k = 0; k < 9; k++) wA[k] = pack2v(w0s[dz * 9 + k], w0s[dz * 9 + k]);

#pragma unroll
            for (int b = 0; b < 7; b++) {
                const float* rowA = &gs [tz + iz + dz][ty + b][j0];
                const float* rowB = &gs2[tz + iz + dz][ty + b][j0];
#pragma unroll
                for (int c = 0; c < 7; c++) {
                    u64 g2 = ((c & 1) == 0)
                           ? *reinterpret_cast<const u64*>(rowA + c)
                           : *reinterpret_cast<const u64*>(rowB + c - 1);
                    u64 t = abs2(add2(g2, negC));
#pragma unroll
                    for (int dy = 0; dy < 3; dy++) {
                        int iy = b - dy;
                        if (iy < 0 || iy >= 5) continue;
#pragma unroll
                        for (int dx = 0; dx < 3; dx++) {
                            int ix = c - dx;
                            if (ix < 0 || ix >= 5) continue;
                            p[iy * 5 + ix] = fma2(t, wA[dy * 3 + dx], p[iy * 5 + ix]);
                        }
                    }
                }
            }
        }
#pragma unroll
        for (int k = 0; k < 25; k++) p[k] = relu2(p[k]);

        // stage B partial consume: chunk-local packed w1 slice per (iz,jz)
#pragma unroll
        for (int jz = 0; jz < 3; jz++) {
            int dz2 = iz - jz;
            if (dz2 < 0 || dz2 >= 3) continue;
            u64 wB[9];
#pragma unroll
            for (int k = 0; k < 9; k++) wB[k] = pack2v(w1s[dz2 * 9 + k], w1s[dz2 * 9 + k]);
#pragma unroll
            for (int jy = 0; jy < 3; jy++)
#pragma unroll
                for (int dy = 0; dy < 3; dy++)
#pragma unroll
                    for (int jx = 0; jx < 3; jx++)
#pragma unroll
                        for (int dx = 0; dx < 3; dx++)
                            rk[(jz * 3 + jy) * 3 + jx] =
                                fma2(wB[dy * 3 + dx],
                                     p[(jy + dy) * 5 + (jx + dx)],
                                     rk[(jz * 3 + jy) * 3 + jx]);
        }
    }

    // ---- epilogue: weights = dk * relu(rk) + 1e-10; weighted average of x ----
    float num0 = 0.f, den0 = 0.f, num1 = 0.f, den1 = 0.f;
#pragma unroll
    for (int j = 0; j < 27; j++) {
        int jz = j / 9, jy = (j / 3) % 3, jx = j % 3;
        float r0, r1;
        unpack2(rk[j], r0, r1);
        float dk = g_dk[j];
        float wv0 = dk * fmaxf(r0, 0.f) + 1e-10f;
        float wv1 = dk * fmaxf(r1, 0.f) + 1e-10f;
        num0 += xs[tz + jz][ty + jy][j0 + jx] * wv0;
        den0 += wv0;
        num1 += xs[tz + jz][ty + jy][j0 + 1 + jx] * wv1;
        den1 += wv1;
    }
    float* o = &out[(oz * OH + oy) * OW + ox0];
    o[0] = num0 / den0;
    o[1] = num1 / den1;
}

// ---------------------------------------------------------------------------
// inputs (metadata order): x, domain_neighbor, guide_im, rw0, rb0, rw1, rb1,
//                          dw0, db0, dw1, db1
// ---------------------------------------------------------------------------
extern "C" void kernel_launch(void* const* d_in, const int* in_sizes, int n_in,
                              void* d_out, int out_size)
{
    const float* x     = (const float*)d_in[0];
    const float* dn    = (const float*)d_in[1];
    const float* guide = (const float*)d_in[2];
    const float* rw0   = (const float*)d_in[3];
    const float* rb0   = (const float*)d_in[4];
    const float* rw1   = (const float*)d_in[5];
    const float* rb1   = (const float*)d_in[6];
    const float* dw0   = (const float*)d_in[7];
    const float* db0   = (const float*)d_in[8];
    const float* dw1   = (const float*)d_in[9];
    const float* db1   = (const float*)d_in[10];
    float* out = (float*)d_out;

    dk_kernel<<<1, 128>>>(dn, dw0, db0, dw1, db1);

    dim3 grid((OW + TXO - 1) / TXO, OH / TY, OD / TZ);   // 2 x 61 x 13
    jbf_kernel<<<grid, NTHREADS>>>(x, guide, rw0, rb0, rw1, rb1, out);
}